// round 14
// baseline (speedup 1.0000x reference)
#include <cuda_runtime.h>
#include <math.h>

#define FFT_N   2048
#define HALF_N  1024
#define HOP     512
#define NBINS   1025
#define BATCH   4
#define NFRAMES 4000
#define OUT_LEN ((NFRAMES - 1) * HOP)   // 2047488 trimmed output per batch

// Bank-conflict padding: insert one slot every 16
#define PAD(i) ((i) + ((i) >> 4))

// 131 MB scratch for windowed frames [B, F, 2048]
__device__ float  g_frames[(size_t)BATCH * NFRAMES * FFT_N];
// Tables (built by init kernel each launch; deterministic)
__device__ float2 g_tw1024[HALF_N];      // e^{+i*pi*k/1024}, k=0..1023 (pack twiddles)
__device__ float2 g_tws[544];            // e^{+i*pi*n/512}, padded at PAD(n), n=0..511
__device__ float  g_win[FFT_N];          // periodic Hann

// ---------------------------------------------------------------------------
// Kernel 0: build tables.
// ---------------------------------------------------------------------------
__global__ __launch_bounds__(1024) void init_tables_kernel()
{
    const int i = threadIdx.x;           // 0..1023
    float s, c;
    sincospif(i * (1.0f / HALF_N), &s, &c);
    g_tw1024[i] = make_float2(c, s);
    if (i < 512) {
        float s2, c2;
        sincospif(i * (1.0f / 512.0f), &s2, &c2);
        g_tws[PAD(i)] = make_float2(c2, s2);
    }
    g_win[2 * i]     = 0.5f - 0.5f * cospif((2 * i)     * (1.0f / HALF_N));
    g_win[2 * i + 1] = 0.5f - 0.5f * cospif((2 * i + 1) * (1.0f / HALF_N));
}

// ---------------------------------------------------------------------------
// Kernel 1: per-frame irfft(2048) via packed 1024-pt complex inverse FFT
// (radix-4; stage 0 fused into the pack, stage 4 fused into the unpack,
// stages 1-3 in shared memory), then Hann window, store to scratch.
// One block (256 threads) per frame.
// ---------------------------------------------------------------------------
__global__ __launch_bounds__(256) void istft_frames_kernel(
    const float* __restrict__ sr,
    const float* __restrict__ si,
    float* __restrict__ frames)
{
    __shared__ float2 sh[PAD(HALF_N - 1) + 2];   // padded 1024 entries
    __shared__ float2 shtw[544];                 // padded stage twiddles

    const int bf  = blockIdx.x;                 // 0 .. B*F-1
    const int tid = threadIdx.x;                // 0 .. 255
    const float* __restrict__ xr = sr + (size_t)bf * NBINS;
    const float* __restrict__ xi = si + (size_t)bf * NBINS;

    // cache stage twiddle table (raw copy incl. padding holes)
    #pragma unroll
    for (int i = tid; i < 544; i += 256) shtw[i] = g_tws[i];

    // --- Pack + fused stage 0 -------------------------------------------
    // Z[k] = E[k] + i*O[k], pre-scaled by 1/2048. For k = q*256 + tid the
    // base-4 digit-reversed position is r4(k) = 4*rev4(tid) + q, so the four
    // values this thread computes form exactly one stage-0 radix-4 butterfly
    // group (h=1, all twiddles = 1). Butterfly in registers, then store.
    // irfft (C2R) ignores imag parts of DC and Nyquist bins -> zero them
    // (both appear only in the k==0 iteration, i.e. tid==0,q==0).
    float2 z[4];
    #pragma unroll
    for (int q = 0; q < 4; q++) {
        const int k = tid + q * 256;            // 0..1023
        const int m = HALF_N - k;               // 1..1024
        const float xkr = xr[k];
        const float xmr = xr[m];
        float xki = xi[k];
        float xmi = xi[m];
        if (k == 0) { xki = 0.0f; xmi = 0.0f; }
        const float scale = 1.0f / 2048.0f;
        const float Er = (xkr + xmr) * scale;
        const float Ei = (xki - xmi) * scale;
        const float Dr = (xkr - xmr) * scale;
        const float Di = (xki + xmi) * scale;
        const float2 tw = g_tw1024[k];          // e^{+i*pi*k/1024}
        const float Or = tw.x * Dr - tw.y * Di;
        const float Oi = tw.x * Di + tw.y * Dr;
        z[q] = make_float2(Er - Oi, Ei + Or);
    }
    {
        // base = 4 * rev4(tid): 8-bit bit-reverse, then swap adjacent pairs
        const int rb8 = __brev(tid) >> 24;
        const int r48 = ((rb8 & 0x55) << 1) | ((rb8 >> 1) & 0x55);
        const int base = r48 << 2;
        // stage-0 butterfly (twiddles = 1): A=z[0], B=z[1], C=z[2], D=z[3]
        const float apc_r = z[0].x + z[2].x, apc_i = z[0].y + z[2].y;
        const float amc_r = z[0].x - z[2].x, amc_i = z[0].y - z[2].y;
        const float bpd_r = z[1].x + z[3].x, bpd_i = z[1].y + z[3].y;
        const float bmd_r = z[1].x - z[3].x, bmd_i = z[1].y - z[3].y;
        sh[PAD(base)]     = make_float2(apc_r + bpd_r, apc_i + bpd_i);
        sh[PAD(base + 1)] = make_float2(amc_r - bmd_i, amc_i + bmd_r);
        sh[PAD(base + 2)] = make_float2(apc_r - bpd_r, apc_i - bpd_i);
        sh[PAD(base + 3)] = make_float2(amc_r + bmd_i, amc_i - bmd_r);
    }
    __syncthreads();

    // --- Stages 1-3 in shared memory (inverse radix-4 DIT) ---------------
    // Twiddles: W = e^{+2*pi*i/(4h)}; W^p -> table[p*256/h], W^2p -> table[p*512/h],
    // W^3p = W^p * W^2p (complex mul; avoids table-range overflow).
    #pragma unroll
    for (int st = 1; st <= 3; st++) {
        const int h  = 1 << (2 * st);
        const int p  = tid & (h - 1);
        const int j  = ((tid >> (2 * st)) << (2 * st + 2)) + p;
        const int n1 = p << (8 - 2 * st);       // p * 256/h  (< 256)
        const int n2 = p << (9 - 2 * st);       // p * 512/h  (< 512)
        const float2 tw1 = shtw[PAD(n1)];
        const float2 tw2 = shtw[PAD(n2)];
        const float2 tw3 = make_float2(tw1.x * tw2.x - tw1.y * tw2.y,
                                       tw1.x * tw2.y + tw1.y * tw2.x);
        const float2 a = sh[PAD(j)];
        const float2 b = sh[PAD(j + h)];
        const float2 c = sh[PAD(j + 2 * h)];
        const float2 d = sh[PAD(j + 3 * h)];
        const float Br = b.x * tw1.x - b.y * tw1.y, Bi = b.x * tw1.y + b.y * tw1.x;
        const float Cr = c.x * tw2.x - c.y * tw2.y, Ci = c.x * tw2.y + c.y * tw2.x;
        const float Dr = d.x * tw3.x - d.y * tw3.y, Di = d.x * tw3.y + d.y * tw3.x;
        const float apc_r = a.x + Cr, apc_i = a.y + Ci;
        const float amc_r = a.x - Cr, amc_i = a.y - Ci;
        const float bpd_r = Br + Dr,  bpd_i = Bi + Di;
        const float bmd_r = Br - Dr,  bmd_i = Bi - Di;
        sh[PAD(j)]         = make_float2(apc_r + bpd_r, apc_i + bpd_i);
        sh[PAD(j + h)]     = make_float2(amc_r - bmd_i, amc_i + bmd_r);
        sh[PAD(j + 2 * h)] = make_float2(apc_r - bpd_r, apc_i - bpd_i);
        sh[PAD(j + 3 * h)] = make_float2(amc_r + bmd_i, amc_i - bmd_r);
        __syncthreads();
    }

    // --- Fused stage 4 + unpack + window + store -------------------------
    // st=4: h=256, p=tid, j=tid; reads sh[tid + q*256] — exactly the unpack
    // indices. Butterfly in registers, then x[2n]=Re, x[2n+1]=Im, window, store.
    {
        const float2 tw1 = shtw[PAD(tid)];          // table[p*256/h] = table[tid]
        const float2 tw2 = shtw[PAD(2 * tid)];      // table[p*512/h] = table[2*tid]
        const float2 tw3 = make_float2(tw1.x * tw2.x - tw1.y * tw2.y,
                                       tw1.x * tw2.y + tw1.y * tw2.x);
        const float2 a = sh[PAD(tid)];
        const float2 b = sh[PAD(tid + 256)];
        const float2 c = sh[PAD(tid + 512)];
        const float2 d = sh[PAD(tid + 768)];
        const float Br = b.x * tw1.x - b.y * tw1.y, Bi = b.x * tw1.y + b.y * tw1.x;
        const float Cr = c.x * tw2.x - c.y * tw2.y, Ci = c.x * tw2.y + c.y * tw2.x;
        const float Dr = d.x * tw3.x - d.y * tw3.y, Di = d.x * tw3.y + d.y * tw3.x;
        const float apc_r = a.x + Cr, apc_i = a.y + Ci;
        const float amc_r = a.x - Cr, amc_i = a.y - Ci;
        const float bpd_r = Br + Dr,  bpd_i = Bi + Di;
        const float bmd_r = Br - Dr,  bmd_i = Bi - Di;
        float2 y[4];
        y[0] = make_float2(apc_r + bpd_r, apc_i + bpd_i);
        y[1] = make_float2(amc_r - bmd_i, amc_i + bmd_r);
        y[2] = make_float2(apc_r - bpd_r, apc_i - bpd_i);
        y[3] = make_float2(amc_r + bmd_i, amc_i - bmd_r);

        const float2* __restrict__ win2 = reinterpret_cast<const float2*>(g_win);
        float2* __restrict__ out2 =
            reinterpret_cast<float2*>(frames + (size_t)bf * FFT_N);
        #pragma unroll
        for (int q = 0; q < 4; q++) {
            const int n = tid + q * 256;
            const float2 w = win2[n];
            out2[n] = make_float2(y[q].x * w.x, y[q].y * w.y);
        }
    }
}

// ---------------------------------------------------------------------------
// Kernel 2: gather-based overlap-add + window_sumsquare normalize + trim.
// Deterministic (no atomics). One thread per trimmed output sample.
// ---------------------------------------------------------------------------
__global__ __launch_bounds__(256) void istft_ola_kernel(
    const float* __restrict__ frames,
    float* __restrict__ out)
{
    const int i = blockIdx.x * 256 + threadIdx.x;   // 0 .. OUT_LEN-1
    const int b = blockIdx.y;
    if (i >= OUT_LEN) return;

    const int t = i + (FFT_N / 2);                  // untrimmed position
    int fhi = t >> 9;                               // t / HOP
    int flo = fhi - 3;
    if (fhi > NFRAMES - 1) fhi = NFRAMES - 1;
    if (flo < 0) flo = 0;

    const float* __restrict__ fb = frames + (size_t)b * NFRAMES * FFT_N;
    float acc = 0.0f, wsq = 0.0f;
    #pragma unroll 4
    for (int f = flo; f <= fhi; f++) {
        const int j = t - (f << 9);                 // 0 .. 2047
        const float w = g_win[j];
        acc += fb[(size_t)f * FFT_N + j];
        wsq += w * w;
    }
    const float tiny = 1.17549435e-38f;             // np.finfo(float32).tiny
    const float denom = (wsq > tiny) ? wsq : 1.0f;
    out[(size_t)b * OUT_LEN + i] = acc / denom;
}

// ---------------------------------------------------------------------------
extern "C" void kernel_launch(void* const* d_in, const int* in_sizes, int n_in,
                              void* d_out, int out_size)
{
    const float* spec_real = (const float*)d_in[0];
    const float* spec_imag = (const float*)d_in[1];
    float* out = (float*)d_out;

    float* frames;
    cudaGetSymbolAddress((void**)&frames, g_frames);

    init_tables_kernel<<<1, 1024>>>();
    istft_frames_kernel<<<BATCH * NFRAMES, 256>>>(spec_real, spec_imag, frames);

    dim3 grid2((OUT_LEN + 255) / 256, BATCH);
    istft_ola_kernel<<<grid2, 256>>>(frames, out);
}

// round 15
// speedup vs baseline: 1.1286x; 1.1286x over previous
#include <cuda_runtime.h>
#include <math.h>

#define FFT_N   2048
#define HALF_N  1024
#define HOP     512
#define NBINS   1025
#define BATCH   4
#define NFRAMES 4000
#define OUT_LEN ((NFRAMES - 1) * HOP)   // 2047488 trimmed output per batch

// Bank-conflict padding: insert one slot every 16
#define PAD(i) ((i) + ((i) >> 4))

// 131 MB scratch for windowed frames [B, F, 2048]
__device__ float  g_frames[(size_t)BATCH * NFRAMES * FFT_N];
// Tables (built by init kernel each launch; deterministic)
__device__ float2 g_tw1024[HALF_N];      // e^{+i*pi*k/1024}, k=0..1023 (pack twiddles)
__device__ float2 g_tws[544];            // e^{+i*pi*n/512}, padded at PAD(n), n=0..511
__device__ float  g_win[FFT_N];          // periodic Hann

// ---------------------------------------------------------------------------
// Kernel 0: build tables (widened: 8 blocks x 128 threads).
// ---------------------------------------------------------------------------
__global__ __launch_bounds__(128) void init_tables_kernel()
{
    const int i = blockIdx.x * 128 + threadIdx.x;   // 0..1023
    float s, c;
    sincospif(i * (1.0f / HALF_N), &s, &c);
    g_tw1024[i] = make_float2(c, s);
    if (i < 512) {
        float s2, c2;
        sincospif(i * (1.0f / 512.0f), &s2, &c2);
        g_tws[PAD(i)] = make_float2(c2, s2);
    }
    g_win[2 * i]     = 0.5f - 0.5f * cospif((2 * i)     * (1.0f / HALF_N));
    g_win[2 * i + 1] = 0.5f - 0.5f * cospif((2 * i + 1) * (1.0f / HALF_N));
}

// Inverse radix-4 butterfly, twiddles = 1 (in place).
__device__ __forceinline__ void bf4_unit(float2& A, float2& B, float2& C, float2& D)
{
    const float apc_r = A.x + C.x, apc_i = A.y + C.y;
    const float amc_r = A.x - C.x, amc_i = A.y - C.y;
    const float bpd_r = B.x + D.x, bpd_i = B.y + D.y;
    const float bmd_r = B.x - D.x, bmd_i = B.y - D.y;
    A = make_float2(apc_r + bpd_r, apc_i + bpd_i);
    B = make_float2(amc_r - bmd_i, amc_i + bmd_r);
    C = make_float2(apc_r - bpd_r, apc_i - bpd_i);
    D = make_float2(amc_r + bmd_i, amc_i - bmd_r);
}

// Inverse radix-4 butterfly with twiddles tw1 (B), tw2 (C), tw3=tw1*tw2 (D).
__device__ __forceinline__ void bf4_tw(float2& A, float2& B, float2& C, float2& D,
                                       const float2 tw1, const float2 tw2)
{
    const float2 tw3 = make_float2(tw1.x * tw2.x - tw1.y * tw2.y,
                                   tw1.x * tw2.y + tw1.y * tw2.x);
    const float Br = B.x * tw1.x - B.y * tw1.y, Bi = B.x * tw1.y + B.y * tw1.x;
    const float Cr = C.x * tw2.x - C.y * tw2.y, Ci = C.x * tw2.y + C.y * tw2.x;
    const float Dr = D.x * tw3.x - D.y * tw3.y, Di = D.x * tw3.y + D.y * tw3.x;
    const float apc_r = A.x + Cr, apc_i = A.y + Ci;
    const float amc_r = A.x - Cr, amc_i = A.y - Ci;
    const float bpd_r = Br + Dr,  bpd_i = Bi + Di;
    const float bmd_r = Br - Dr,  bmd_i = Bi - Di;
    A = make_float2(apc_r + bpd_r, apc_i + bpd_i);
    B = make_float2(amc_r - bmd_i, amc_i + bmd_r);
    C = make_float2(apc_r - bpd_r, apc_i - bpd_i);
    D = make_float2(amc_r + bmd_i, amc_i - bmd_r);
}

// ---------------------------------------------------------------------------
// Kernel 1: per-frame irfft(2048) via packed 1024-pt complex inverse FFT.
// Radix-4, 5 stages; TWO stages per smem round-trip:
//   [pack + st0 + st1 in regs] -> smem -> [st2 + st3 in regs] -> smem ->
//   [st4 + unpack + window + gmem store]
// 64 threads per frame, 16 float2 registers each; 4 frames per 256-thr block.
// ---------------------------------------------------------------------------
__global__ __launch_bounds__(256) void istft_frames_kernel(
    const float* __restrict__ sr,
    const float* __restrict__ si,
    float* __restrict__ frames)
{
    __shared__ float2 sh[4][PAD(HALF_N - 1) + 2];   // per-frame padded 1024
    __shared__ float2 shtw[544];                    // padded stage twiddles

    const int tid = threadIdx.x;                // 0..255
    const int fr  = tid >> 6;                   // frame slot 0..3
    const int u   = tid & 63;                   // thread within frame
    const int bf  = blockIdx.x * 4 + fr;        // 0 .. B*F-1
    const float* __restrict__ xr = sr + (size_t)bf * NBINS;
    const float* __restrict__ xi = si + (size_t)bf * NBINS;

    // cache stage twiddle table (raw copy incl. padding holes)
    #pragma unroll
    for (int i = tid; i < 544; i += 256) shtw[i] = g_tws[i];

    // --- Pack + stages 0,1 in registers ---------------------------------
    // Thread u owns reversed positions [16*B, 16*B+16), B = rev4_3(u).
    // Element v = 4*e1 + q there corresponds to k = q*256 + e1*64 + u.
    // irfft ignores imag of DC and Nyquist -> zero (only at k==0: u=0,q=0,e1=0).
    float2 z[16];
    #pragma unroll
    for (int e1 = 0; e1 < 4; e1++) {
        #pragma unroll
        for (int q = 0; q < 4; q++) {
            const int k = q * 256 + e1 * 64 + u;    // 0..1023
            const int m = HALF_N - k;               // 1..1024
            const float xkr = xr[k];
            const float xmr = xr[m];
            float xki = xi[k];
            float xmi = xi[m];
            if (k == 0) { xki = 0.0f; xmi = 0.0f; }
            const float scale = 1.0f / 2048.0f;
            const float Er = (xkr + xmr) * scale;
            const float Ei = (xki - xmi) * scale;
            const float Dr = (xkr - xmr) * scale;
            const float Di = (xki + xmi) * scale;
            const float2 tw = g_tw1024[k];          // e^{+i*pi*k/1024}
            const float Or = tw.x * Dr - tw.y * Di;
            const float Oi = tw.x * Di + tw.y * Dr;
            z[4 * e1 + q] = make_float2(Er - Oi, Ei + Or);
        }
    }
    // stage 0 (h=1, twiddles=1): combine over q for fixed e1
    #pragma unroll
    for (int e1 = 0; e1 < 4; e1++)
        bf4_unit(z[4 * e1 + 0], z[4 * e1 + 1], z[4 * e1 + 2], z[4 * e1 + 3]);
    // stage 1 (h=4): elements v = qp + 4c, twiddle p = qp
    #pragma unroll
    for (int qp = 0; qp < 4; qp++) {
        const float2 tw1 = shtw[PAD(qp << 6)];
        const float2 tw2 = shtw[PAD(qp << 7)];
        bf4_tw(z[qp], z[qp + 4], z[qp + 8], z[qp + 12], tw1, tw2);
    }
    // store block [16B, 16B+16)
    {
        const int B = ((u & 3) << 4) | (u & 12) | (u >> 4);  // base-4 3-digit rev
        const int base = B << 4;
        #pragma unroll
        for (int v = 0; v < 16; v++) sh[fr][PAD(base + v)] = z[v];
    }
    __syncthreads();

    // --- Stages 2,3 in registers ----------------------------------------
    // Thread (s = u>>4, o = u&15) owns positions 256*s + o + 16*t, t=0..15.
    {
        const int s = u >> 4, o = u & 15;
        const int pbase = 256 * s + o;
        #pragma unroll
        for (int t = 0; t < 16; t++) z[t] = sh[fr][PAD(pbase + 16 * t)];
        // stage 2 (h=16): groups t = 4c+m over m, twiddle p = o (same all groups)
        {
            const float2 tw1 = shtw[PAD(o << 4)];
            const float2 tw2 = shtw[PAD(o << 5)];
            #pragma unroll
            for (int c = 0; c < 4; c++)
                bf4_tw(z[4 * c], z[4 * c + 1], z[4 * c + 2], z[4 * c + 3], tw1, tw2);
        }
        // stage 3 (h=64): groups t = m0 + 4m over m, twiddle p = o + 16*m0
        #pragma unroll
        for (int m0 = 0; m0 < 4; m0++) {
            const int p = o + 16 * m0;              // < 64
            const float2 tw1 = shtw[PAD(p << 2)];
            const float2 tw2 = shtw[PAD(p << 3)];
            bf4_tw(z[m0], z[m0 + 4], z[m0 + 8], z[m0 + 12], tw1, tw2);
        }
        #pragma unroll
        for (int t = 0; t < 16; t++) sh[fr][PAD(pbase + 16 * t)] = z[t];
    }
    __syncthreads();

    // --- Stage 4 + unpack + window + store ------------------------------
    // Thread u handles groups o3 = u + 64*j; x[2n]=Re z[n], x[2n+1]=Im z[n].
    {
        const float2* __restrict__ win2 = reinterpret_cast<const float2*>(g_win);
        float2* __restrict__ out2 =
            reinterpret_cast<float2*>(frames + (size_t)bf * FFT_N);
        #pragma unroll
        for (int j = 0; j < 4; j++) {
            const int o3 = u + 64 * j;              // < 256
            float2 A = sh[fr][PAD(o3)];
            float2 Bv = sh[fr][PAD(o3 + 256)];
            float2 Cv = sh[fr][PAD(o3 + 512)];
            float2 Dv = sh[fr][PAD(o3 + 768)];
            const float2 tw1 = shtw[PAD(o3)];
            const float2 tw2 = shtw[PAD(2 * o3)];
            bf4_tw(A, Bv, Cv, Dv, tw1, tw2);
            const float2 y[4] = {A, Bv, Cv, Dv};
            #pragma unroll
            for (int q = 0; q < 4; q++) {
                const int n = o3 + 256 * q;
                const float2 w = win2[n];
                out2[n] = make_float2(y[q].x * w.x, y[q].y * w.y);
            }
        }
    }
}

// ---------------------------------------------------------------------------
// Kernel 2: gather-based overlap-add + window_sumsquare normalize + trim.
// Deterministic (no atomics). One thread per trimmed output sample.
// ---------------------------------------------------------------------------
__global__ __launch_bounds__(256) void istft_ola_kernel(
    const float* __restrict__ frames,
    float* __restrict__ out)
{
    const int i = blockIdx.x * 256 + threadIdx.x;   // 0 .. OUT_LEN-1
    const int b = blockIdx.y;
    if (i >= OUT_LEN) return;

    const int t = i + (FFT_N / 2);                  // untrimmed position
    int fhi = t >> 9;                               // t / HOP
    int flo = fhi - 3;
    if (fhi > NFRAMES - 1) fhi = NFRAMES - 1;
    if (flo < 0) flo = 0;

    const float* __restrict__ fb = frames + (size_t)b * NFRAMES * FFT_N;
    float acc = 0.0f, wsq = 0.0f;
    #pragma unroll 4
    for (int f = flo; f <= fhi; f++) {
        const int j = t - (f << 9);                 // 0 .. 2047
        const float w = g_win[j];
        acc += fb[(size_t)f * FFT_N + j];
        wsq += w * w;
    }
    const float tiny = 1.17549435e-38f;             // np.finfo(float32).tiny
    const float denom = (wsq > tiny) ? wsq : 1.0f;
    out[(size_t)b * OUT_LEN + i] = acc / denom;
}

// ---------------------------------------------------------------------------
extern "C" void kernel_launch(void* const* d_in, const int* in_sizes, int n_in,
                              void* d_out, int out_size)
{
    const float* spec_real = (const float*)d_in[0];
    const float* spec_imag = (const float*)d_in[1];
    float* out = (float*)d_out;

    float* frames;
    cudaGetSymbolAddress((void**)&frames, g_frames);

    init_tables_kernel<<<8, 128>>>();
    istft_frames_kernel<<<BATCH * NFRAMES / 4, 256>>>(spec_real, spec_imag, frames);

    dim3 grid2((OUT_LEN + 255) / 256, BATCH);
    istft_ola_kernel<<<grid2, 256>>>(frames, out);
}